// round 1
// baseline (speedup 1.0000x reference)
#include <cuda_runtime.h>

#define N_ 256
#define M_ 512
#define D_ 64
#define EPSF 1e-6f
#define INFF 1e30f

// ---------------- device scratch (no allocations allowed) ----------------
__device__ float g_dists[M_ * N_];   // d[m][n]
__device__ float g_w[N_ * N_];       // w[n][t] = p_back[n][t] (lower-tri used)
__device__ float g_wN[N_];           // p_back[N][t]
__device__ float g_Cbar[N_ * N_];    // Cbar[n][t], in-place across m (INF init)
__device__ float g_C[M_ * N_];       // C[m][t]
__device__ int   g_flags[M_];        // flags[m] = number of columns row m completed
__device__ int   g_ticket;

// ---------------- acquire / release helpers ----------------
__device__ __forceinline__ int ld_acquire(const int* p) {
    int v;
    asm volatile("ld.acquire.gpu.global.b32 %0, [%1];" : "=r"(v) : "l"(p) : "memory");
    return v;
}
__device__ __forceinline__ void st_release(int* p, int v) {
    asm volatile("st.release.gpu.global.b32 [%0], %1;" :: "l"(p), "r"(v) : "memory");
}

// ---------------- kernel: reset mutable state each launch ----------------
__global__ void pal_reset_kernel() {
    int idx = blockIdx.x * blockDim.x + threadIdx.x;
    if (idx < N_ * N_) g_Cbar[idx] = INFF;
    if (idx < M_)      g_flags[idx] = 0;
    if (idx == 0)      g_ticket = 0;
}

// ---------------- kernel: pairwise L2 distances ----------------
__global__ void pal_dists_kernel(const float* __restrict__ x,
                                 const float* __restrict__ y) {
    __shared__ float sx[D_];
    int m = blockIdx.x;
    int t = threadIdx.x;
    if (t < D_) sx[t] = x[m * D_ + t];
    __syncthreads();
    const float4* y4 = reinterpret_cast<const float4*>(y + (size_t)t * D_);
    float acc = 0.f;
#pragma unroll
    for (int i = 0; i < D_ / 4; i++) {
        float4 v = y4[i];
        float d0 = sx[4 * i + 0] - v.x;
        float d1 = sx[4 * i + 1] - v.y;
        float d2 = sx[4 * i + 2] - v.z;
        float d3 = sx[4 * i + 3] - v.w;
        acc += d0 * d0 + d1 * d1 + d2 * d2 + d3 * d3;
    }
    g_dists[m * N_ + t] = sqrtf(acc);
}

// ---------------- kernel: reachability p, mixing weights w ----------------
// Single block of 512 threads. Threads 0..256 carry p[i]; the sequential
// recurrence is p += p[nb] * q[:, nb] for nb = 0..N-1 (p[nb] = value at step nb).
__global__ void pal_reach_kernel(const float* __restrict__ q) {
    __shared__ float sp[N_ + 1];
    int tid = threadIdx.x;
    bool act = (tid <= N_);
    float preg = (tid == 0) ? 1.f : 0.f;
    if (tid == 0) sp[0] = 1.f;
    float qv = act ? q[(size_t)tid * N_] : 0.f;
    __syncthreads();
    for (int nb = 0; nb < N_; nb++) {
        float pnb = sp[nb];                         // broadcast
        float qn = (act && (nb + 1 < N_)) ? q[(size_t)tid * N_ + nb + 1] : 0.f;
        preg = fmaf(pnb, qv, preg);
        qv = qn;
        if (tid == nb + 1) sp[nb + 1] = preg;       // value read at next step
        __syncthreads();
    }
    if (act) sp[tid] = preg;                        // final p
    __syncthreads();
    float pN = sp[N_];
    // w[n][t] = p[t] * q[n][t] / (p[n] + eps)
    for (int idx = tid; idx < N_ * N_; idx += blockDim.x) {
        int n = idx >> 8;
        int t = idx & (N_ - 1);
        g_w[idx] = sp[t] * q[idx] / (sp[n] + EPSF);
    }
    if (tid < N_) g_wN[tid] = sp[tid] * q[N_ * N_ + tid] / (pN + EPSF);
}

// ---------------- kernel: wavefront DP ----------------
// One block per row m (ticketed for scheduling-order safety). Thread t owns
// column t. Per column n: cbar[t] = d[m][n] + min(C[m][t], C[m-1][t], Cbar[n][t])
// for t<n; C[m][n] = sum_t w[n][t]*cbar[t]; Cbar[n][t] updated in place.
__global__ void pal_dp_kernel(float* __restrict__ out) {
    __shared__ float sm_d[N_];
    __shared__ float sm8[8];
    __shared__ int   sm_m;

    int tid = threadIdx.x;
    if (tid == 0) sm_m = atomicAdd(&g_ticket, 1);
    __syncthreads();
    const int m = sm_m;

    sm_d[tid] = g_dists[m * N_ + tid];
    __syncthreads();

    const int* flagp = (m > 0) ? &g_flags[m - 1] : (const int*)0;
    int fcache = 0;

    float Cc = 0.f;       // C[m][tid], valid after step tid
    float Cp = INFF;      // C[m-1][tid], loaded at step tid
    float wreg = g_w[1 * N_ + tid];   // prefetch w row 1 (row 0 unused)

    // ---- step 0 ----
    if (m > 0) {
        if (tid == 0) {
            while (fcache < 1) {
                fcache = ld_acquire(flagp);
                if (fcache < 1) __nanosleep(64);
            }
        }
        __syncthreads();
    }
    if (tid == 0) {
        float base = (m > 0) ? g_C[(m - 1) * N_] : 0.f;
        Cc = sm_d[0] + base;
        g_C[m * N_] = Cc;
        st_release(&g_flags[m], 1);
    }

    // ---- steps n = 1..N-1 ----
    for (int n = 1; n < N_; n++) {
        if (m > 0) {
            if (tid == 0) {
                while (fcache < n + 1) {
                    fcache = ld_acquire(flagp);
                    if (fcache < n + 1) __nanosleep(64);
                }
            }
            __syncthreads();   // block-scope acq through tid0's acquire
        }
        if (tid == n && m > 0) Cp = g_C[(m - 1) * N_ + n];

        float contrib = 0.f;
        if (tid < n) {
            float cin = g_Cbar[n * N_ + tid];
            float mn  = fminf(Cc, fminf(Cp, cin));
            float cb  = sm_d[n] + mn;
            g_Cbar[n * N_ + tid] = cb;
            contrib = wreg * cb;
        }
        if (n + 1 < N_) wreg = g_w[(n + 1) * N_ + tid];   // prefetch next w row

        // block reduce (8 warps)
        float v = contrib;
#pragma unroll
        for (int o = 16; o; o >>= 1) v += __shfl_xor_sync(0xffffffffu, v, o);
        if ((tid & 31) == 0) sm8[tid >> 5] = v;
        __syncthreads();
        float r = sm8[0] + sm8[1] + sm8[2] + sm8[3]
                + sm8[4] + sm8[5] + sm8[6] + sm8[7];
        if (tid == n) Cc = r;
        __syncthreads();   // protect sm8 reuse; order Cbar stores before release
        if (tid == 0) {
            g_C[m * N_ + n] = r;
            st_release(&g_flags[m], n + 1);
        }
    }

    // ---- final reduction: sum_t p_back[N][t] * C[M-1][t] ----
    if (m == M_ - 1) {
        float v = g_wN[tid] * Cc;
#pragma unroll
        for (int o = 16; o; o >>= 1) v += __shfl_xor_sync(0xffffffffu, v, o);
        if ((tid & 31) == 0) sm8[tid >> 5] = v;
        __syncthreads();
        if (tid == 0) {
            out[0] = sm8[0] + sm8[1] + sm8[2] + sm8[3]
                   + sm8[4] + sm8[5] + sm8[6] + sm8[7];
        }
    }
}

// ---------------- launch ----------------
extern "C" void kernel_launch(void* const* d_in, const int* in_sizes, int n_in,
                              void* d_out, int out_size) {
    const float* x = (const float*)d_in[0];   // (512, 64)
    const float* y = (const float*)d_in[1];   // (256, 64)
    const float* q = (const float*)d_in[2];   // (257, 256)
    float* out = (float*)d_out;

    pal_reset_kernel<<<256, 256>>>();
    pal_dists_kernel<<<M_, N_>>>(x, y);
    pal_reach_kernel<<<1, 512>>>(q);
    pal_dp_kernel<<<M_, N_>>>(out);
}

// round 2
// speedup vs baseline: 1.4564x; 1.4564x over previous
#include <cuda_runtime.h>

#define N_ 256
#define M_ 512
#define D_ 64
#define ROWS_ 8
#define CTAS_ (M_ / ROWS_)   // 64
#define EPSF 1e-6f
#define INFF 1e30f

// ---------------- device scratch (no allocations allowed) ----------------
__device__ float g_dists[M_ * N_];   // d[m][n]
__device__ float g_w[N_ * N_];       // w[n][t]
__device__ float g_wN[N_];           // p_back[N][t]
__device__ float g_Cbar[N_ * N_];    // Cbar[n][t] at CTA boundaries (INF init)
__device__ float g_C[M_ * N_];       // C[m][t], only boundary rows used
__device__ int   g_flags[CTAS_];     // steps completed by CTA's last warp
__device__ int   g_ticket;

// ---------------- acquire / release helpers ----------------
__device__ __forceinline__ int ld_acquire(const int* p) {
    int v;
    asm volatile("ld.acquire.gpu.global.b32 %0, [%1];" : "=r"(v) : "l"(p) : "memory");
    return v;
}
__device__ __forceinline__ void st_release(int* p, int v) {
    asm volatile("st.release.gpu.global.b32 [%0], %1;" :: "l"(p), "r"(v) : "memory");
}

// ---------------- kernel: reset mutable state each launch ----------------
__global__ void pal_reset_kernel() {
    int idx = blockIdx.x * blockDim.x + threadIdx.x;
    if (idx < N_ * N_) g_Cbar[idx] = INFF;
    if (idx < CTAS_)   g_flags[idx] = 0;
    if (idx == 0)      g_ticket = 0;
}

// ---------------- kernel: pairwise L2 distances ----------------
__global__ void pal_dists_kernel(const float* __restrict__ x,
                                 const float* __restrict__ y) {
    __shared__ float sx[D_];
    int m = blockIdx.x;
    int t = threadIdx.x;
    if (t < D_) sx[t] = x[m * D_ + t];
    __syncthreads();
    const float4* y4 = reinterpret_cast<const float4*>(y + (size_t)t * D_);
    float acc = 0.f;
#pragma unroll
    for (int i = 0; i < D_ / 4; i++) {
        float4 v = y4[i];
        float d0 = sx[4 * i + 0] - v.x;
        float d1 = sx[4 * i + 1] - v.y;
        float d2 = sx[4 * i + 2] - v.z;
        float d3 = sx[4 * i + 3] - v.w;
        acc += d0 * d0 + d1 * d1 + d2 * d2 + d3 * d3;
    }
    g_dists[m * N_ + t] = sqrtf(acc);
}

// ---------------- kernel: reachability p, mixing weights w ----------------
__global__ void pal_reach_kernel(const float* __restrict__ q) {
    __shared__ float sp[N_ + 1];
    int tid = threadIdx.x;
    bool act = (tid <= N_);
    float preg = (tid == 0) ? 1.f : 0.f;
    if (tid == 0) sp[0] = 1.f;
    float qv = act ? q[(size_t)tid * N_] : 0.f;
    __syncthreads();
    for (int nb = 0; nb < N_; nb++) {
        float pnb = sp[nb];
        float qn = (act && (nb + 1 < N_)) ? q[(size_t)tid * N_ + nb + 1] : 0.f;
        preg = fmaf(pnb, qv, preg);
        qv = qn;
        if (tid == nb + 1) sp[nb + 1] = preg;
        __syncthreads();
    }
    if (act) sp[tid] = preg;
    __syncthreads();
    float pN = sp[N_];
    for (int idx = tid; idx < N_ * N_; idx += blockDim.x) {
        int n = idx >> 8;
        int t = idx & (N_ - 1);
        g_w[idx] = sp[t] * q[idx] / (sp[n] + EPSF);
    }
    if (tid < N_) g_wN[tid] = sp[tid] * q[N_ * N_ + tid] / (pN + EPSF);
}

// ---------------- kernel: lockstep wavefront DP ----------------
// CTA `bid` owns rows [bid*8, bid*8+8). Warp w = row bid*8+w. All warps
// advance in lockstep: at tick T, warp w executes column n = T - w.
// Row-to-row data (Cbar rows, C vectors) flows through shared memory;
// CTA boundaries use the global flag/g_C/g_Cbar protocol.
__global__ void __launch_bounds__(256, 1) pal_dp_kernel(float* __restrict__ out) {
    __shared__ float sd[ROWS_][N_];            // distance rows
    __shared__ float sC[ROWS_][N_];            // C[m][t] per local row
    __shared__ float sCp[N_];                  // producer C vector for warp 0 (from global)
    __shared__ float sbuf[ROWS_ - 1][2][N_];   // cbar double buffers between adjacent rows
    __shared__ float sm8[8];
    __shared__ int   sm_bid;

    const int tid = threadIdx.x;
    const int w   = tid >> 5;
    const int l   = tid & 31;

    if (tid == 0) sm_bid = atomicAdd(&g_ticket, 1);
    __syncthreads();
    const int bid = sm_bid;
    const int m   = bid * ROWS_ + w;

#pragma unroll
    for (int r = 0; r < ROWS_; r++)
        sd[r][tid] = g_dists[(bid * ROWS_ + r) * N_ + tid];
    __syncthreads();

    const bool gprod = (w == 0 && bid > 0);   // producer is previous CTA (global)
    const bool mzero = (m == 0);
    const int* gflag = &g_flags[(bid > 0) ? bid - 1 : 0];
    const int  prow  = m - 1;
    int fc = 0;

    for (int T = 0; T < N_ + ROWS_ - 1; T++) {
        const int n = T - w;
        if (n >= 0 && n < N_) {
            float cpn = INFF;
            if (gprod) {
                // need previous CTA's last row to have completed column n
                while (fc < n + 1) {
                    fc = ld_acquire(gflag);
                    if (fc < n + 1) __nanosleep(32);
                }
                cpn = g_C[prow * N_ + n];      // broadcast load (all lanes same addr)
                if (l == 0) sCp[n] = cpn;      // archive for later columns' min
            }
            const float dmn = sd[w][n];

            if (n == 0) {
                float base = mzero ? 0.f : (w == 0 ? cpn : sC[w - 1][0]);
                float c0 = dmn + base;
                if (l == 0) {
                    sC[w][0] = c0;
                    if (w == ROWS_ - 1) {
                        g_C[m * N_ + 0] = c0;
                        st_release(&g_flags[bid], 1);
                    }
                }
            } else {
                const int nch = (n + 31) >> 5;   // chunks with any active lane
                float acc = 0.f;
                for (int ch = 0; ch < nch; ch++) {
                    const int t = (ch << 5) + l;
                    float cprev = mzero ? INFF : (w == 0 ? sCp[t] : sC[w - 1][t]);
                    float cbarp = mzero ? INFF
                                 : (w == 0 ? g_Cbar[n * N_ + t]
                                           : sbuf[w - 1][n & 1][t]);
                    float mn = fminf(sC[w][t], fminf(cprev, cbarp));
                    float cb = dmn + mn;
                    if (t < n) {
                        float wt = __ldg(&g_w[n * N_ + t]);
                        acc = fmaf(wt, cb, acc);
                        if (w < ROWS_ - 1) sbuf[w][n & 1][t] = cb;
                        else               g_Cbar[n * N_ + t] = cb;
                    }
                }
#pragma unroll
                for (int o = 16; o; o >>= 1)
                    acc += __shfl_xor_sync(0xffffffffu, acc, o);
                __syncwarp();   // order all lanes' cbar stores before the release
                if (l == 0) {
                    sC[w][n] = acc;
                    if (w == ROWS_ - 1) {
                        g_C[m * N_ + n] = acc;
                        st_release(&g_flags[bid], n + 1);
                    }
                }
            }
        }
        __syncthreads();   // lockstep tick boundary (orders all smem traffic)
    }

    // ---- final reduction: sum_t p_back[N][t] * C[M-1][t] ----
    if (bid == CTAS_ - 1) {
        float v = g_wN[tid] * sC[ROWS_ - 1][tid];
#pragma unroll
        for (int o = 16; o; o >>= 1) v += __shfl_xor_sync(0xffffffffu, v, o);
        if (l == 0) sm8[w] = v;
        __syncthreads();
        if (tid == 0) {
            out[0] = sm8[0] + sm8[1] + sm8[2] + sm8[3]
                   + sm8[4] + sm8[5] + sm8[6] + sm8[7];
        }
    }
}

// ---------------- launch ----------------
extern "C" void kernel_launch(void* const* d_in, const int* in_sizes, int n_in,
                              void* d_out, int out_size) {
    const float* x = (const float*)d_in[0];   // (512, 64)
    const float* y = (const float*)d_in[1];   // (256, 64)
    const float* q = (const float*)d_in[2];   // (257, 256)
    float* out = (float*)d_out;

    pal_reset_kernel<<<256, 256>>>();
    pal_dists_kernel<<<M_, N_>>>(x, y);
    pal_reach_kernel<<<1, 512>>>(q);
    pal_dp_kernel<<<CTAS_, 256>>>(out);
}

// round 3
// speedup vs baseline: 2.4039x; 1.6506x over previous
#include <cuda_runtime.h>

#define N_ 256
#define M_ 512
#define D_ 64
#define ROWS_ 8
#define CTAS_ (M_ / ROWS_)   // 64
#define CHUNKS_ 8            // N_/32
#define EPSF 1e-6f
#define INFF 1e30f

// ---------------- device scratch (no allocations allowed) ----------------
__device__ float g_dists[M_ * N_];   // d[m][n]
__device__ float g_w[N_ * N_];       // w[n][t]
__device__ float g_wN[N_];           // p_back[N][t]
__device__ float g_Cbar[N_ * N_];    // Cbar[n][t] at CTA boundaries
__device__ float g_C[M_ * N_];       // C[m][t], boundary rows only
__device__ int   g_flags[CTAS_];     // columns completed by CTA's last warp
__device__ int   g_ticket;

// ---------------- acquire / release helpers ----------------
__device__ __forceinline__ int ld_acquire(const int* p) {
    int v;
    asm volatile("ld.acquire.gpu.global.b32 %0, [%1];" : "=r"(v) : "l"(p) : "memory");
    return v;
}
__device__ __forceinline__ void st_release(int* p, int v) {
    asm volatile("st.release.gpu.global.b32 [%0], %1;" :: "l"(p), "r"(v) : "memory");
}

// ---------------- kernel: reset mutable state each launch ----------------
__global__ void pal_reset_kernel() {
    int idx = blockIdx.x * blockDim.x + threadIdx.x;
    if (idx < N_ * N_) g_Cbar[idx] = INFF;
    if (idx < CTAS_)   g_flags[idx] = 0;
    if (idx == 0)      g_ticket = 0;
}

// ---------------- kernel: pairwise L2 distances ----------------
__global__ void pal_dists_kernel(const float* __restrict__ x,
                                 const float* __restrict__ y) {
    __shared__ float sx[D_];
    int m = blockIdx.x;
    int t = threadIdx.x;
    if (t < D_) sx[t] = x[m * D_ + t];
    __syncthreads();
    const float4* y4 = reinterpret_cast<const float4*>(y + (size_t)t * D_);
    float acc = 0.f;
#pragma unroll
    for (int i = 0; i < D_ / 4; i++) {
        float4 v = y4[i];
        float d0 = sx[4 * i + 0] - v.x;
        float d1 = sx[4 * i + 1] - v.y;
        float d2 = sx[4 * i + 2] - v.z;
        float d3 = sx[4 * i + 3] - v.w;
        acc += d0 * d0 + d1 * d1 + d2 * d2 + d3 * d3;
    }
    g_dists[m * N_ + t] = sqrtf(acc);
}

// ---------------- kernel: reachability p, mixing weights w ----------------
__global__ void pal_reach_kernel(const float* __restrict__ q) {
    __shared__ float sp[N_ + 1];
    int tid = threadIdx.x;
    bool act = (tid <= N_);
    float preg = (tid == 0) ? 1.f : 0.f;
    if (tid == 0) sp[0] = 1.f;
    const float4* qrow = act ? reinterpret_cast<const float4*>(q + (size_t)tid * N_)
                             : reinterpret_cast<const float4*>(q);
    float4 qcur = qrow[0];
    float4 qnxt = qrow[1];
    __syncthreads();
    for (int nb = 0; nb < N_; nb++) {
        float pnb = sp[nb];
        int s = nb & 3;
        float qv = (s == 0) ? qcur.x : (s == 1) ? qcur.y : (s == 2) ? qcur.z : qcur.w;
        preg = fmaf(pnb, qv, preg);
        if (s == 3) {
            qcur = qnxt;
            int g = (nb >> 2) + 2;
            qnxt = qrow[g < N_ / 4 ? g : N_ / 4 - 1];
        }
        if (tid == nb + 1) sp[nb + 1] = preg;
        __syncthreads();
    }
    if (act) sp[tid] = preg;
    __syncthreads();
    float pN = sp[N_];
    for (int idx = tid; idx < N_ * N_; idx += blockDim.x) {
        int n = idx >> 8;
        int t = idx & (N_ - 1);
        g_w[idx] = sp[t] * q[idx] / (sp[n] + EPSF);
    }
    if (tid < N_) g_wN[tid] = sp[tid] * q[N_ * N_ + tid] / (pN + EPSF);
}

// ---------------- kernel: lockstep wavefront DP ----------------
// CTA bid owns rows [bid*8, bid*8+8), warp w = one row, lockstep ticks
// (one __syncthreads per tick, warp w at column n = T - w). All chunk loops
// are fully unrolled (8 chunks, t<n predication) for MLP; w rows and
// cross-CTA Cbar/C data are prefetched one tick ahead.
__global__ void __launch_bounds__(256, 1) pal_dp_kernel(float* __restrict__ out) {
    __shared__ float sd[ROWS_][N_];            // distance rows
    __shared__ float sC[ROWS_][N_];            // published C rows
    __shared__ float sCp[N_];                  // prev-CTA last C row (warp0 archive)
    __shared__ float sbuf[ROWS_ - 1][2][N_];   // cbar double buffers
    __shared__ float sm8[8];
    __shared__ int   sm_bid;

    const int tid = threadIdx.x;
    const int w   = tid >> 5;
    const int l   = tid & 31;

    if (tid == 0) sm_bid = atomicAdd(&g_ticket, 1);
    __syncthreads();
    const int bid = sm_bid;
    const int m   = bid * ROWS_ + w;

#pragma unroll
    for (int r = 0; r < ROWS_; r++)
        sd[r][tid] = g_dists[(bid * ROWS_ + r) * N_ + tid];
    __syncthreads();

    const bool mzero = (m == 0);
    const bool gw0   = (w == 0 && bid > 0);
    int* gflag = &g_flags[(bid > 0) ? bid - 1 : 0];
    const float* gCprev = &g_C[(bid > 0 ? m - 1 : 0) * N_];

    float Cown[CHUNKS_];
#pragma unroll
    for (int c = 0; c < CHUNKS_; c++) Cown[c] = INFF;
    float wv[CHUNKS_];     // w row for current column (prefetched)
    float cbn[CHUNKS_];    // prefetched g_Cbar row (warp0, bid>0)
    float cpn = INFF;      // prefetched g_C[m-1][n]
    int  fc = 0;
    bool havep = false;

    for (int T = 0; T < N_ + ROWS_ - 1; T++) {
        const int n = T - w;
        if (n == 0) {
            float base = 0.f;
            if (!mzero) {
                if (w == 0) {
                    while (fc < 1) fc = ld_acquire(gflag);
                    base = gCprev[0];
                    if (l == 0) sCp[0] = base;
                } else {
                    base = sC[w - 1][0];
                }
            }
            float c0 = sd[w][0] + base;
            if (l == 0) { Cown[0] = c0; sC[w][0] = c0; }
            if (w == ROWS_ - 1 && l == 0) {
                g_C[m * N_ + 0] = c0;
                st_release(&g_flags[bid], 1);
            }
            // prefetch w row 1 for next tick
#pragma unroll
            for (int c = 0; c < CHUNKS_; c++) wv[c] = g_w[1 * N_ + c * 32 + l];
            // warp0: try to prefetch column-1 cross-CTA data
            if (gw0) {
                fc = ld_acquire(gflag);
                if (fc >= 2) {
                    cpn = gCprev[1];
#pragma unroll
                    for (int c = 0; c < CHUNKS_; c++)
                        cbn[c] = g_Cbar[1 * N_ + c * 32 + l];
                    havep = true;
                } else havep = false;
            }
        } else if (n >= 1 && n < N_) {
            int fc_new = fc;
            if (gw0) {
                fc_new = ld_acquire(gflag);   // issued early, consumed at tick end
                if (!havep) {
                    while (fc < n + 1) fc = ld_acquire(gflag);
                    cpn = gCprev[n];
#pragma unroll
                    for (int c = 0; c < CHUNKS_; c++)
                        cbn[c] = g_Cbar[n * N_ + c * 32 + l];
                }
                if (l == 0) sCp[n] = cpn;
            }
            const float dmn = sd[w][n];
            const int   par = n & 1;
            float acc = 0.f;
            float cbst[CHUNKS_];
#pragma unroll
            for (int c = 0; c < CHUNKS_; c++) {
                const int t = c * 32 + l;
                float cprev, cbarp;
                if (mzero)       { cprev = INFF;          cbarp = INFF; }
                else if (w == 0) { cprev = sCp[t];        cbarp = cbn[c]; }
                else             { cprev = sC[w - 1][t];  cbarp = sbuf[w - 1][par][t]; }
                float mn = fminf(Cown[c], fminf(cprev, cbarp));
                float cb = dmn + mn;
                cbst[c] = cb;
                if (t < n) acc = fmaf(wv[c], cb, acc);
            }
            if (w < ROWS_ - 1) {
#pragma unroll
                for (int c = 0; c < CHUNKS_; c++) {
                    int t = c * 32 + l;
                    if (t < n) sbuf[w][par][t] = cbst[c];
                }
            } else {
#pragma unroll
                for (int c = 0; c < CHUNKS_; c++) {
                    int t = c * 32 + l;
                    if (t < n) g_Cbar[n * N_ + t] = cbst[c];
                }
            }
            // prefetch w row n+1 (clamped; hidden behind barrier)
            const int nn = (n + 1 < N_) ? n + 1 : N_ - 1;
#pragma unroll
            for (int c = 0; c < CHUNKS_; c++) wv[c] = g_w[nn * N_ + c * 32 + l];
            // warp reduce (all lanes get the sum)
#pragma unroll
            for (int o = 16; o; o >>= 1)
                acc += __shfl_xor_sync(0xffffffffu, acc, o);
            // update own C register (static predicated writes)
#pragma unroll
            for (int c = 0; c < CHUNKS_; c++)
                if ((n >> 5) == c && (n & 31) == l) Cown[c] = acc;
            if (l == 0) sC[w][n] = acc;
            if (w == ROWS_ - 1) {
                __syncwarp();   // order all lanes' g_Cbar stores before release
                if (l == 0) {
                    g_C[m * N_ + n] = acc;
                    st_release(&g_flags[bid], n + 1);
                }
            }
            // warp0: prefetch next column's cross-CTA data if flag permits
            if (gw0) {
                if (fc_new > fc) fc = fc_new;
                if (fc >= n + 2 && n + 1 < N_) {
                    cpn = gCprev[n + 1];
#pragma unroll
                    for (int c = 0; c < CHUNKS_; c++)
                        cbn[c] = g_Cbar[(n + 1) * N_ + c * 32 + l];
                    havep = true;
                } else havep = false;
            }
        }
        __syncthreads();   // lockstep tick boundary
    }

    // ---- final reduction: sum_t p_back[N][t] * C[M-1][t] ----
    if (bid == CTAS_ - 1) {
        float v = g_wN[tid] * sC[ROWS_ - 1][tid];
#pragma unroll
        for (int o = 16; o; o >>= 1) v += __shfl_xor_sync(0xffffffffu, v, o);
        if (l == 0) sm8[w] = v;
        __syncthreads();
        if (tid == 0) {
            out[0] = sm8[0] + sm8[1] + sm8[2] + sm8[3]
                   + sm8[4] + sm8[5] + sm8[6] + sm8[7];
        }
    }
}

// ---------------- launch ----------------
extern "C" void kernel_launch(void* const* d_in, const int* in_sizes, int n_in,
                              void* d_out, int out_size) {
    const float* x = (const float*)d_in[0];   // (512, 64)
    const float* y = (const float*)d_in[1];   // (256, 64)
    const float* q = (const float*)d_in[2];   // (257, 256)
    float* out = (float*)d_out;

    pal_reset_kernel<<<256, 256>>>();
    pal_dists_kernel<<<M_, N_>>>(x, y);
    pal_reach_kernel<<<1, 512>>>(q);
    pal_dp_kernel<<<CTAS_, 256>>>(out);
}

// round 5
// speedup vs baseline: 6.3330x; 2.6345x over previous
#include <cuda_runtime.h>

#define N_ 256
#define M_ 512
#define D_ 64
#define ROWS_ 8
#define CTAS_ (M_ / ROWS_)   // 64
#define CHUNKS_ 8            // N_/32
#define EPSF 1e-6f
#define INFF 1e30f

// ---------------- device scratch (no allocations allowed) ----------------
__device__ float g_dists[M_ * N_];      // d[m][n]
__device__ float g_w[N_ * N_];          // w[n][t]
__device__ float g_wN[N_];              // p_back[N][t]
__device__ float g_Cbar[N_ * N_];       // Cbar[n][t] at CTA boundaries
__device__ float g_C[M_ * N_];          // C[m][t], boundary rows only
__device__ int   g_flags[CTAS_ * 16];   // padded flags, index bid*16
__device__ int   g_ticket;

// ---------------- acquire / release helpers ----------------
__device__ __forceinline__ int ld_acquire(const int* p) {
    int v;
    asm volatile("ld.acquire.gpu.global.b32 %0, [%1];" : "=r"(v) : "l"(p) : "memory");
    return v;
}
__device__ __forceinline__ void st_release(int* p, int v) {
    asm volatile("st.release.gpu.global.b32 [%0], %1;" :: "l"(p), "r"(v) : "memory");
}
__device__ __forceinline__ int lds_acquire(const int* p) {
    int v;
    unsigned a = (unsigned)__cvta_generic_to_shared((const void*)p);
    asm volatile("ld.acquire.cta.shared.b32 %0, [%1];" : "=r"(v) : "r"(a) : "memory");
    return v;
}
__device__ __forceinline__ void sts_release(int* p, int v) {
    unsigned a = (unsigned)__cvta_generic_to_shared((void*)p);
    asm volatile("st.release.cta.shared.b32 [%0], %1;" :: "r"(a), "r"(v) : "memory");
}

// ---------------- kernel: reset mutable state each launch ----------------
__global__ void pal_reset_kernel() {
    int idx = blockIdx.x * blockDim.x + threadIdx.x;
    if (idx < CTAS_ * 16) g_flags[idx] = 0;
    if (idx == 0)         g_ticket = 0;
}

// ---------------- kernel: pairwise L2 distances ----------------
__global__ void pal_dists_kernel(const float* __restrict__ x,
                                 const float* __restrict__ y) {
    __shared__ float sx[D_];
    int m = blockIdx.x;
    int t = threadIdx.x;
    if (t < D_) sx[t] = x[m * D_ + t];
    __syncthreads();
    const float4* y4 = reinterpret_cast<const float4*>(y + (size_t)t * D_);
    float acc = 0.f;
#pragma unroll
    for (int i = 0; i < D_ / 4; i++) {
        float4 v = y4[i];
        float d0 = sx[4 * i + 0] - v.x;
        float d1 = sx[4 * i + 1] - v.y;
        float d2 = sx[4 * i + 2] - v.z;
        float d3 = sx[4 * i + 3] - v.w;
        acc += d0 * d0 + d1 * d1 + d2 * d2 + d3 * d3;
    }
    g_dists[m * N_ + t] = sqrtf(acc);
}

// ---------------- kernel: reachability p, mixing weights w ----------------
__global__ void pal_reach_kernel(const float* __restrict__ q) {
    __shared__ float sp[N_ + 1];
    int tid = threadIdx.x;
    bool act = (tid <= N_);
    float preg = (tid == 0) ? 1.f : 0.f;
    if (tid == 0) sp[0] = 1.f;
    const float4* qrow = act ? reinterpret_cast<const float4*>(q + (size_t)tid * N_)
                             : reinterpret_cast<const float4*>(q);
    float4 qcur = qrow[0];
    float4 qnxt = qrow[1];
    __syncthreads();
    for (int nb = 0; nb < N_; nb++) {
        float pnb = sp[nb];
        int s = nb & 3;
        float qv = (s == 0) ? qcur.x : (s == 1) ? qcur.y : (s == 2) ? qcur.z : qcur.w;
        preg = fmaf(pnb, qv, preg);
        if (s == 3) {
            qcur = qnxt;
            int g = (nb >> 2) + 2;
            qnxt = qrow[g < N_ / 4 ? g : N_ / 4 - 1];
        }
        if (tid == nb + 1) sp[nb + 1] = preg;
        __syncthreads();
    }
    if (act) sp[tid] = preg;
    __syncthreads();
    float pN = sp[N_];
    for (int idx = tid; idx < N_ * N_; idx += blockDim.x) {
        int n = idx >> 8;
        int t = idx & (N_ - 1);
        g_w[idx] = sp[t] * q[idx] / (sp[n] + EPSF);
    }
    if (tid < N_) g_wN[tid] = sp[tid] * q[N_ * N_ + tid] / (pN + EPSF);
}

// ---------------- kernel: decoupled wavefront DP ----------------
// CTA bid owns rows [bid*8, bid*8+8), one warp per row. No CTA barrier in the
// main loop: warp-to-warp handoff via per-warp smem flags (release/acquire at
// cta scope), with a depth-4 cbar ring + consumer-progress backpressure.
// Data flags are released BEFORE the reduce (downstream needs cbar row n and
// C[m-1][<=n-1] only). CTA boundaries use g_flags / g_C / g_Cbar (gpu scope).
// NOTE: cross-CTA mutable data (g_Cbar, g_C) is read with PLAIN coherent
// loads — never __ldg/ld.global.nc, which is outside acquire ordering.
__global__ void __launch_bounds__(256, 1) pal_dp_kernel(float* __restrict__ out) {
    __shared__ float sd[ROWS_][N_];             // distance rows
    __shared__ float sC[ROWS_][N_];             // published C rows (warps 0..6)
    __shared__ float sbuf[ROWS_ - 1][4][N_];    // cbar rings between adjacent rows
    __shared__ int   sflag[ROWS_];              // data flags (columns published)
    __shared__ int   rflag[ROWS_];              // consumer progress flags
    __shared__ int   sm_bid;

    const int tid = threadIdx.x;
    const int w   = tid >> 5;
    const int l   = tid & 31;

    if (tid == 0) sm_bid = atomicAdd(&g_ticket, 1);
    if (tid < ROWS_) { sflag[tid] = 0; rflag[tid] = 0; }
    __syncthreads();
    const int bid = sm_bid;
    const int m   = bid * ROWS_ + w;

#pragma unroll
    for (int r = 0; r < ROWS_; r++)
        sd[r][tid] = __ldg(&g_dists[(bid * ROWS_ + r) * N_ + tid]);
    __syncthreads();

    const bool mz  = (m == 0);
    const bool gup = (w == 0 && bid > 0);            // upstream is previous CTA
    const int* gflag = &g_flags[(bid > 0 ? bid - 1 : 0) * 16];
    int*       myflag = &g_flags[bid * 16];
    const float* gCprev = &g_C[(bid > 0 ? m - 1 : 0) * N_];
    volatile const float* gCbar_v = g_Cbar;          // coherent mutable reads
    volatile const float* gCprev_v = gCprev;

    float Cown[CHUNKS_], Cpr[CHUNKS_], wv[CHUNKS_], cbnP[CHUNKS_];
#pragma unroll
    for (int c = 0; c < CHUNKS_; c++) { Cown[c] = INFF; Cpr[c] = INFF; cbnP[c] = INFF; }
    float vprevP = 0.f;
    bool  havep = false;
    int   fc = 0, fcache = 0, rcache = 0;
    float dcur = sd[w][0];

    // ---- column 0 ----
    {
        float base = 0.f;
        if (!mz) {
            if (w == 0) {
                while (fc < 1) fc = ld_acquire(gflag);
                base = gCprev_v[0];
            } else {
                while (fcache < 1) fcache = lds_acquire(&sflag[w - 1]);
                base = sC[w - 1][0];
            }
        }
        float c0 = dcur + base;
        if (l == 0) {
            Cown[0] = c0;
            if (!mz) Cpr[0] = base;
            if (w < ROWS_ - 1) { sC[w][0] = c0; sts_release(&sflag[w], 1); }
            else               { g_C[m * N_ + 0] = c0; st_release(myflag, 1); }
        }
        dcur = sd[w][1];
#pragma unroll
        for (int c = 0; c < CHUNKS_; c++) wv[c] = __ldg(&g_w[1 * N_ + c * 32 + l]);
        if (gup) {
            fc = ld_acquire(gflag);
            if (fc >= 2) {
#pragma unroll
                for (int c = 0; c < CHUNKS_; c++)
                    cbnP[c] = gCbar_v[1 * N_ + c * 32 + l];
                vprevP = gCprev_v[0];
                havep = true;
            }
        }
    }

    // ---- columns 1..N-1 (per-warp loop, no CTA barrier) ----
    for (int n = 1; n < N_; n++) {
        const int slot = n & 3;
        float cbarv[CHUNKS_];
        float vprev = INFF;

        if (!mz) {
            if (w == 0) {
                if (havep) {
#pragma unroll
                    for (int c = 0; c < CHUNKS_; c++) cbarv[c] = cbnP[c];
                    vprev = vprevP;
                } else {
                    while (fc < n + 1) fc = ld_acquire(gflag);
#pragma unroll
                    for (int c = 0; c < CHUNKS_; c++)
                        cbarv[c] = gCbar_v[n * N_ + c * 32 + l];
                    vprev = gCprev_v[n - 1];
                }
            } else {
                if (fcache < n + 1) {
                    do { fcache = lds_acquire(&sflag[w - 1]); } while (fcache < n + 1);
                }
#pragma unroll
                for (int c = 0; c < CHUNKS_; c++)
                    cbarv[c] = sbuf[w - 1][slot][c * 32 + l];
                vprev = sC[w - 1][n - 1];
            }
        } else {
#pragma unroll
            for (int c = 0; c < CHUNKS_; c++) cbarv[c] = INFF;
        }

        // registerize C[m-1][n-1]
        {
            const int cc = (n - 1) >> 5, ll = (n - 1) & 31;
#pragma unroll
            for (int c = 0; c < CHUNKS_; c++)
                if (c == cc && l == ll) Cpr[c] = vprev;
        }

        const float dmn = dcur;
        float acc0 = 0.f, acc1 = 0.f;
        float cbst[CHUNKS_];
#pragma unroll
        for (int c = 0; c < CHUNKS_; c++) {
            const int t = c * 32 + l;
            float mn = fminf(Cown[c], fminf(Cpr[c], cbarv[c]));
            float cb = dmn + mn;
            cbst[c] = cb;
            float pr = (t < n) ? wv[c] * cb : 0.f;
            if (c & 1) acc1 += pr; else acc0 += pr;
        }
        float acc = acc0 + acc1;

        // publish cbar row + data flag BEFORE the reduce
        if (w < ROWS_ - 1) {
            if (n >= 4 && rcache < n - 3) {
                do { rcache = lds_acquire(&rflag[w + 1]); } while (rcache < n - 3);
            }
#pragma unroll
            for (int c = 0; c < CHUNKS_; c++) {
                int t = c * 32 + l;
                if (t < n) sbuf[w][slot][t] = cbst[c];
            }
            __syncwarp();
            if (l == 0) sts_release(&sflag[w], n + 1);
            if (l == 1 && w >= 1) sts_release(&rflag[w], n + 1);
        } else {
#pragma unroll
            for (int c = 0; c < CHUNKS_; c++) {
                int t = c * 32 + l;
                if (t < n) g_Cbar[n * N_ + t] = cbst[c];
            }
            __syncwarp();
            if (l == 0) st_release(myflag, n + 1);
            if (l == 1) sts_release(&rflag[ROWS_ - 1], n + 1);
        }

        // warp reduce (own-column chain only)
#pragma unroll
        for (int o = 16; o; o >>= 1)
            acc += __shfl_xor_sync(0xffffffffu, acc, o);

        {
            const int cc = n >> 5, ll = n & 31;
#pragma unroll
            for (int c = 0; c < CHUNKS_; c++)
                if (c == cc && l == ll) Cown[c] = acc;
        }
        if (w < ROWS_ - 1) { if (l == 0) sC[w][n] = acc; }
        else               { if (l == 0) g_C[m * N_ + n] = acc; }

        // prefetch next column inputs
        const int nn = (n + 1 < N_) ? n + 1 : N_ - 1;
        dcur = sd[w][nn];
#pragma unroll
        for (int c = 0; c < CHUNKS_; c++) wv[c] = __ldg(&g_w[nn * N_ + c * 32 + l]);
        if (gup) {
            fc = ld_acquire(gflag);
            if (fc >= n + 2 && n + 1 < N_) {
#pragma unroll
                for (int c = 0; c < CHUNKS_; c++)
                    cbnP[c] = gCbar_v[(n + 1) * N_ + c * 32 + l];
                vprevP = gCprev_v[n];
                havep = true;
            } else havep = false;
        }
    }

    // ---- final: out = sum_t p_back[N][t] * C[M-1][t] ----
    if (bid == CTAS_ - 1 && w == ROWS_ - 1) {
        float v = 0.f;
#pragma unroll
        for (int c = 0; c < CHUNKS_; c++)
            v += __ldg(&g_wN[c * 32 + l]) * Cown[c];
#pragma unroll
        for (int o = 16; o; o >>= 1)
            v += __shfl_xor_sync(0xffffffffu, v, o);
        if (l == 0) out[0] = v;
    }
}

// ---------------- launch ----------------
extern "C" void kernel_launch(void* const* d_in, const int* in_sizes, int n_in,
                              void* d_out, int out_size) {
    const float* x = (const float*)d_in[0];   // (512, 64)
    const float* y = (const float*)d_in[1];   // (256, 64)
    const float* q = (const float*)d_in[2];   // (257, 256)
    float* out = (float*)d_out;

    pal_reset_kernel<<<1, 1024>>>();
    pal_dists_kernel<<<M_, N_>>>(x, y);
    pal_reach_kernel<<<1, 512>>>(q);
    pal_dp_kernel<<<CTAS_, 256>>>(out);
}